// round 13
// baseline (speedup 1.0000x reference)
#include <cuda_runtime.h>
#include <cuda_bf16.h>
#include <mma.h>
#include <cstdint>
#include <cstddef>

using namespace nvcuda;

// Problem constants
#define B_   4
#define T_   2048
#define DM_  512
#define H_   8
#define DH_  64
#define BH_  (B_ * H_)     // 32
#define M_   (B_ * T_)     // 8192

// Scratch (device globals; no allocations allowed)
__device__ float g_q   [(size_t)BH_ * T_ * DH_]; // (b,h,t,d)
__device__ float g_k   [(size_t)BH_ * T_ * DH_]; // (b,h,t,d)
__device__ float g_v   [(size_t)BH_ * T_ * DH_]; // (b,h,t,d)
__device__ float g_ctx [(size_t)M_ * DM_];       // (b*T+t, h*64+d)
__device__ float g_part[(size_t)BH_ * T_ * 32];  // per-row partial exp sums
__device__ float g_inv [(size_t)BH_ * T_];       // 1/rowsum

// fp32 -> bf16 hi + bf16 lo split (hi+lo reproduces fp32 to ~2^-17 rel)
__device__ __forceinline__ void split4(float4 v, uint2& hi, uint2& lo) {
    __nv_bfloat16 h0 = __float2bfloat16(v.x), h1 = __float2bfloat16(v.y);
    __nv_bfloat16 h2 = __float2bfloat16(v.z), h3 = __float2bfloat16(v.w);
    __nv_bfloat16 l0 = __float2bfloat16(v.x - __bfloat162float(h0));
    __nv_bfloat16 l1 = __float2bfloat16(v.y - __bfloat162float(h1));
    __nv_bfloat16 l2 = __float2bfloat16(v.z - __bfloat162float(h2));
    __nv_bfloat16 l3 = __float2bfloat16(v.w - __bfloat162float(h3));
    uint16_t uh0 = *(uint16_t*)&h0, uh1 = *(uint16_t*)&h1;
    uint16_t uh2 = *(uint16_t*)&h2, uh3 = *(uint16_t*)&h3;
    uint16_t ul0 = *(uint16_t*)&l0, ul1 = *(uint16_t*)&l1;
    uint16_t ul2 = *(uint16_t*)&l2, ul3 = *(uint16_t*)&l3;
    hi.x = (uint32_t)uh0 | ((uint32_t)uh1 << 16);
    hi.y = (uint32_t)uh2 | ((uint32_t)uh3 << 16);
    lo.x = (uint32_t)ul0 | ((uint32_t)ul1 << 16);
    lo.y = (uint32_t)ul2 | ((uint32_t)ul3 << 16);
}

typedef wmma::fragment<wmma::matrix_a, 16, 16, 16, __nv_bfloat16, wmma::row_major> FragA;
typedef wmma::fragment<wmma::matrix_b, 16, 16, 16, __nv_bfloat16, wmma::col_major> FragBc;
typedef wmma::fragment<wmma::matrix_b, 16, 16, 16, __nv_bfloat16, wmma::row_major> FragBr;
typedef wmma::fragment<wmma::accumulator, 16, 16, 16, float> FragC;

// ---------------------------------------------------------------------------
// Projection GEMM (wmma split-bf16): out[m,n] = sum_k X[m,k]*W[n,k] + bias[n]
// CTA tile 128(M) x 64(N), BK=32, 256 threads = 8 warps (4m x 2n), warp 32x32.
// mode 0: scatter to (b,h,t,d); mode 2: row-major m*512+n
// ---------------------------------------------------------------------------
__global__ __launch_bounds__(256) void gemm_proj(
    const float* __restrict__ X, const float* __restrict__ W,
    const float* __restrict__ bias, float* __restrict__ out, int mode)
{
    __shared__ __align__(16) char sbuf[36864];
    __nv_bfloat16* Ah = (__nv_bfloat16*)sbuf;      // [128][40]
    __nv_bfloat16* Al = Ah + 5120;
    __nv_bfloat16* Bh = Ah + 10240;                // [64][40]
    __nv_bfloat16* Bl = Ah + 12800;
    float* Cs = (float*)sbuf;                      // [128][72] (epilogue reuse)

    const int tid = threadIdx.x;
    const int wid = tid >> 5;
    const int m0 = blockIdx.y * 128;
    const int n0 = blockIdx.x * 64;
    const int wm0 = (wid >> 1) * 32;
    const int wn0 = (wid & 1) * 32;

    FragC acc[2][2];
    #pragma unroll
    for (int i = 0; i < 2; i++)
        #pragma unroll
        for (int j = 0; j < 2; j++) wmma::fill_fragment(acc[i][j], 0.f);

    float4 px[4], pw[2];

    #pragma unroll
    for (int u = 0; u < 4; u++) {
        const int idx = u * 256 + tid, r = idx >> 3, c = idx & 7;
        px[u] = *(const float4*)&X[(size_t)(m0 + r) * 512 + c * 4];
    }
    #pragma unroll
    for (int u = 0; u < 2; u++) {
        const int idx = u * 256 + tid, r = idx >> 3, c = idx & 7;
        pw[u] = *(const float4*)&W[(size_t)(n0 + r) * 512 + c * 4];
    }
    #pragma unroll
    for (int u = 0; u < 4; u++) {
        const int idx = u * 256 + tid, r = idx >> 3, c = idx & 7;
        uint2 hi, lo; split4(px[u], hi, lo);
        *(uint2*)&Ah[r * 40 + c * 4] = hi;
        *(uint2*)&Al[r * 40 + c * 4] = lo;
    }
    #pragma unroll
    for (int u = 0; u < 2; u++) {
        const int idx = u * 256 + tid, r = idx >> 3, c = idx & 7;
        uint2 hi, lo; split4(pw[u], hi, lo);
        *(uint2*)&Bh[r * 40 + c * 4] = hi;
        *(uint2*)&Bl[r * 40 + c * 4] = lo;
    }
    __syncthreads();

    for (int c0 = 0; c0 < 16; c0++) {
        if (c0 < 15) {
            const int k0 = (c0 + 1) * 32;
            #pragma unroll
            for (int u = 0; u < 4; u++) {
                const int idx = u * 256 + tid, r = idx >> 3, c = idx & 7;
                px[u] = *(const float4*)&X[(size_t)(m0 + r) * 512 + k0 + c * 4];
            }
            #pragma unroll
            for (int u = 0; u < 2; u++) {
                const int idx = u * 256 + tid, r = idx >> 3, c = idx & 7;
                pw[u] = *(const float4*)&W[(size_t)(n0 + r) * 512 + k0 + c * 4];
            }
        }

        #pragma unroll
        for (int ks = 0; ks < 32; ks += 16) {
            FragA ah[2], al[2];
            FragBc bh[2], bl[2];
            #pragma unroll
            for (int i = 0; i < 2; i++) {
                wmma::load_matrix_sync(ah[i], &Ah[(wm0 + i * 16) * 40 + ks], 40);
                wmma::load_matrix_sync(al[i], &Al[(wm0 + i * 16) * 40 + ks], 40);
            }
            #pragma unroll
            for (int j = 0; j < 2; j++) {
                wmma::load_matrix_sync(bh[j], &Bh[(wn0 + j * 16) * 40 + ks], 40);
                wmma::load_matrix_sync(bl[j], &Bl[(wn0 + j * 16) * 40 + ks], 40);
            }
            #pragma unroll
            for (int i = 0; i < 2; i++)
                #pragma unroll
                for (int j = 0; j < 2; j++) {
                    wmma::mma_sync(acc[i][j], ah[i], bh[j], acc[i][j]);
                    wmma::mma_sync(acc[i][j], ah[i], bl[j], acc[i][j]);
                    wmma::mma_sync(acc[i][j], al[i], bh[j], acc[i][j]);
                }
        }
        __syncthreads();
        if (c0 < 15) {
            #pragma unroll
            for (int u = 0; u < 4; u++) {
                const int idx = u * 256 + tid, r = idx >> 3, c = idx & 7;
                uint2 hi, lo; split4(px[u], hi, lo);
                *(uint2*)&Ah[r * 40 + c * 4] = hi;
                *(uint2*)&Al[r * 40 + c * 4] = lo;
            }
            #pragma unroll
            for (int u = 0; u < 2; u++) {
                const int idx = u * 256 + tid, r = idx >> 3, c = idx & 7;
                uint2 hi, lo; split4(pw[u], hi, lo);
                *(uint2*)&Bh[r * 40 + c * 4] = hi;
                *(uint2*)&Bl[r * 40 + c * 4] = lo;
            }
            __syncthreads();
        }
    }

    #pragma unroll
    for (int i = 0; i < 2; i++)
        #pragma unroll
        for (int j = 0; j < 2; j++)
            wmma::store_matrix_sync(&Cs[(wm0 + i * 16) * 72 + wn0 + j * 16],
                                    acc[i][j], 72, wmma::mem_row_major);
    __syncthreads();

    #pragma unroll
    for (int u = 0; u < 8; u++) {
        const int idx = u * 256 + tid;
        const int row = idx >> 4, c4 = idx & 15;
        float4 v = *(const float4*)&Cs[row * 72 + c4 * 4];
        float4 bv = *(const float4*)&bias[n0 + c4 * 4];
        v.x += bv.x; v.y += bv.y; v.z += bv.z; v.w += bv.w;
        const int m = m0 + row;
        size_t o;
        if (mode == 0) {
            const int bb = m >> 11, t = m & 2047, head = n0 >> 6;
            o = (((size_t)bb * H_ + head) * T_ + t) * DH_ + c4 * 4;
        } else {
            o = (size_t)m * DM_ + n0 + c4 * 4;
        }
        *(float4*)&out[o] = v;
    }
}

// ---------------------------------------------------------------------------
// QK kernel: E[128q][128t] = exp(Q.K^T/8) per CTA. exp applied on fragments;
// tile staged via smem (reused input bufs) for per-row partial sums (width 32)
// written to g_part; E stored fp32 to graw (attn buffer, unnormalized).
// dynamic smem: Qhi/Qlo/Khi/Kl each [128][72] bf16 = 73728 B; 2 CTAs/SM.
// ---------------------------------------------------------------------------
#define QK_SMEM 73728

__global__ __launch_bounds__(256, 2) void qk_kernel(
    const float* __restrict__ gq, const float* __restrict__ gk,
    float* __restrict__ graw, float* __restrict__ gpart)
{
    extern __shared__ __align__(16) char dsm[];
    __nv_bfloat16* Qh = (__nv_bfloat16*)dsm;   // [128][72]
    __nv_bfloat16* Ql = Qh + 9216;
    __nv_bfloat16* Kh = Qh + 18432;
    __nv_bfloat16* Kl = Qh + 27648;

    const int tid = threadIdx.x;
    const int wid = tid >> 5;
    const int lane = tid & 31;
    const int t0 = blockIdx.x * 128;
    const int q0 = blockIdx.y * 128;
    const int bh = blockIdx.z;

    #pragma unroll
    for (int u = 0; u < 8; u++) {
        const int idx = u * 256 + tid, r = idx >> 4, c = idx & 15;
        float4 v = *(const float4*)&gq[((size_t)bh * T_ + q0 + r) * DH_ + c * 4];
        v.x *= 0.125f; v.y *= 0.125f; v.z *= 0.125f; v.w *= 0.125f;
        uint2 hi, lo; split4(v, hi, lo);
        *(uint2*)&Qh[r * 72 + c * 4] = hi;
        *(uint2*)&Ql[r * 72 + c * 4] = lo;
        float4 w = *(const float4*)&gk[((size_t)bh * T_ + t0 + r) * DH_ + c * 4];
        split4(w, hi, lo);
        *(uint2*)&Kh[r * 72 + c * 4] = hi;
        *(uint2*)&Kl[r * 72 + c * 4] = lo;
    }
    __syncthreads();

    const int wm0 = (wid >> 1) * 32;
    const int wn0 = (wid & 1) * 64;

    FragC acc[2][4];
    #pragma unroll
    for (int i = 0; i < 2; i++)
        #pragma unroll
        for (int j = 0; j < 4; j++) wmma::fill_fragment(acc[i][j], 0.f);

    #pragma unroll
    for (int ks = 0; ks < 64; ks += 16) {
        FragA ah[2], al[2];
        #pragma unroll
        for (int i = 0; i < 2; i++) {
            wmma::load_matrix_sync(ah[i], &Qh[(wm0 + i * 16) * 72 + ks], 72);
            wmma::load_matrix_sync(al[i], &Ql[(wm0 + i * 16) * 72 + ks], 72);
        }
        #pragma unroll
        for (int j = 0; j < 4; j++) {
            FragBc bh, bl;
            wmma::load_matrix_sync(bh, &Kh[(wn0 + j * 16) * 72 + ks], 72);
            wmma::load_matrix_sync(bl, &Kl[(wn0 + j * 16) * 72 + ks], 72);
            #pragma unroll
            for (int i = 0; i < 2; i++) {
                wmma::mma_sync(acc[i][j], ah[i], bh, acc[i][j]);
                wmma::mma_sync(acc[i][j], ah[i], bl, acc[i][j]);
                wmma::mma_sync(acc[i][j], al[i], bh, acc[i][j]);
            }
        }
    }

    // exp on fragment elements (pointwise -> layout agnostic)
    #pragma unroll
    for (int i = 0; i < 2; i++)
        #pragma unroll
        for (int j = 0; j < 4; j++)
            #pragma unroll
            for (int e = 0; e < acc[i][j].num_elements; e++)
                acc[i][j].x[e] = __expf(acc[i][j].x[e]);

    // stage via smem (inputs dead now) for row sums + store
    __syncthreads();
    float* Cw = (float*)dsm + wid * 2048;   // per-warp [32][64]
    #pragma unroll
    for (int i = 0; i < 2; i++)
        #pragma unroll
        for (int j = 0; j < 4; j++)
            wmma::store_matrix_sync(&Cw[(i * 16) * 64 + j * 16], acc[i][j], 64,
                                    wmma::mem_row_major);

    // lane = row within warp tile: sum 64 cols, store E row, write partial
    {
        const int row = q0 + wm0 + lane;
        float* dst = graw + ((size_t)bh * T_ + row) * T_ + t0 + wn0;
        const float* src = Cw + lane * 64;
        float s = 0.f;
        #pragma unroll
        for (int c = 0; c < 16; c++) {
            float4 v = *(const float4*)&src[c * 4];
            s += v.x + v.y + v.z + v.w;
            *(float4*)&dst[c * 4] = v;
        }
        const int pcol = blockIdx.x * 2 + (wn0 >> 6);
        gpart[((size_t)bh * T_ + row) * 32 + pcol] = s;
    }
}

// ---------------------------------------------------------------------------
// Reduce: inv[row] = 1 / sum(part[row][0..31]);  65536 rows.
// ---------------------------------------------------------------------------
__global__ __launch_bounds__(256) void reduce_kernel(
    const float* __restrict__ gpart, float* __restrict__ ginv)
{
    const size_t row = blockIdx.x * 256 + threadIdx.x;
    const float4* p = (const float4*)(gpart + row * 32);
    float s = 0.f;
    #pragma unroll
    for (int i = 0; i < 8; i++) {
        float4 v = p[i];
        s += v.x + v.y + v.z + v.w;
    }
    ginv[row] = 1.f / s;
}

// ---------------------------------------------------------------------------
// PV kernel: ctx[128q][64d] = P @ V, P = E * inv (scaled on load); normalized
// attn written back in-place. BK=32, 64 chunks, reg prefetch. 8 warps.
// ---------------------------------------------------------------------------
__global__ __launch_bounds__(256) void pv_kernel(
    float* __restrict__ gp, const float* __restrict__ gv,
    const float* __restrict__ ginv, float* __restrict__ gctx)
{
    __shared__ __align__(16) char sbuf[29696];
    __shared__ float sinv[128];
    __nv_bfloat16* Ph = (__nv_bfloat16*)sbuf;      // [128][40]
    __nv_bfloat16* Pl = Ph + 5120;
    __nv_bfloat16* Vh = Ph + 10240;                // [32][72]
    __nv_bfloat16* Vl = Ph + 12544;

    const int tid = threadIdx.x;
    const int wid = tid >> 5;
    const int q0 = blockIdx.x * 128;
    const int bh = blockIdx.y;
    const int wm0 = (wid >> 1) * 32;
    const int wn0 = (wid & 1) * 32;

    if (tid < 128) sinv[tid] = ginv[(size_t)bh * T_ + q0 + tid];
    __syncthreads();

    FragC acc[2][2];
    #pragma unroll
    for (int i = 0; i < 2; i++)
        #pragma unroll
        for (int j = 0; j < 2; j++) wmma::fill_fragment(acc[i][j], 0.f);

    float4 pp[4], vv[2];

    // chunk 0: load E, scale by inv
    #pragma unroll
    for (int u = 0; u < 4; u++) {
        const int idx = u * 256 + tid, r = idx >> 3, c = idx & 7;
        pp[u] = *(const float4*)&gp[((size_t)bh * T_ + q0 + r) * T_ + c * 4];
        const float iv = sinv[r];
        pp[u].x *= iv; pp[u].y *= iv; pp[u].z *= iv; pp[u].w *= iv;
    }
    #pragma unroll
    for (int u = 0; u < 2; u++) {
        const int idx = u * 256 + tid, r = idx >> 4, c = idx & 15;
        vv[u] = *(const float4*)&gv[((size_t)bh * T_ + r) * DH_ + c * 4];
    }
    #pragma unroll
    for (int u = 0; u < 4; u++) {
        const int idx = u * 256 + tid, r = idx >> 3, c = idx & 7;
        *(float4*)&gp[((size_t)bh * T_ + q0 + r) * T_ + c * 4] = pp[u];  // normalized attn
        uint2 hi, lo; split4(pp[u], hi, lo);
        *(uint2*)&Ph[r * 40 + c * 4] = hi;
        *(uint2*)&Pl[r * 40 + c * 4] = lo;
    }
    #pragma unroll
    for (int u = 0; u < 2; u++) {
        const int idx = u * 256 + tid, r = idx >> 4, c = idx & 15;
        uint2 hi, lo; split4(vv[u], hi, lo);
        *(uint2*)&Vh[r * 72 + c * 4] = hi;
        *(uint2*)&Vl[r * 72 + c * 4] = lo;
    }
    __syncthreads();

    for (int c0 = 0; c0 < 64; c0++) {
        const int tb = (c0 + 1) * 32;
        if (c0 < 63) {
            #pragma unroll
            for (int u = 0; u < 4; u++) {
                const int idx = u * 256 + tid, r = idx >> 3, c = idx & 7;
                pp[u] = *(const float4*)&gp[((size_t)bh * T_ + q0 + r) * T_ + tb + c * 4];
                const float iv = sinv[r];
                pp[u].x *= iv; pp[u].y *= iv; pp[u].z *= iv; pp[u].w *= iv;
            }
            #pragma unroll
            for (int u = 0; u < 2; u++) {
                const int idx = u * 256 + tid, r = idx >> 4, c = idx & 15;
                vv[u] = *(const float4*)&gv[((size_t)bh * T_ + tb + r) * DH_ + c * 4];
            }
        }

        #pragma unroll
        for (int ks = 0; ks < 32; ks += 16) {
            FragA ah[2], al[2];
            FragBr bh2[2], bl2[2];
            #pragma unroll
            for (int i = 0; i < 2; i++) {
                wmma::load_matrix_sync(ah[i], &Ph[(wm0 + i * 16) * 40 + ks], 40);
                wmma::load_matrix_sync(al[i], &Pl[(wm0 + i * 16) * 40 + ks], 40);
            }
            #pragma unroll
            for (int j = 0; j < 2; j++) {
                wmma::load_matrix_sync(bh2[j], &Vh[ks * 72 + wn0 + j * 16], 72);
                wmma::load_matrix_sync(bl2[j], &Vl[ks * 72 + wn0 + j * 16], 72);
            }
            #pragma unroll
            for (int i = 0; i < 2; i++)
                #pragma unroll
                for (int j = 0; j < 2; j++) {
                    wmma::mma_sync(acc[i][j], ah[i], bh2[j], acc[i][j]);
                    wmma::mma_sync(acc[i][j], ah[i], bl2[j], acc[i][j]);
                    wmma::mma_sync(acc[i][j], al[i], bh2[j], acc[i][j]);
                }
        }
        __syncthreads();
        if (c0 < 63) {
            #pragma unroll
            for (int u = 0; u < 4; u++) {
                const int idx = u * 256 + tid, r = idx >> 3, c = idx & 7;
                *(float4*)&gp[((size_t)bh * T_ + q0 + r) * T_ + tb + c * 4] = pp[u];
                uint2 hi, lo; split4(pp[u], hi, lo);
                *(uint2*)&Ph[r * 40 + c * 4] = hi;
                *(uint2*)&Pl[r * 40 + c * 4] = lo;
            }
            #pragma unroll
            for (int u = 0; u < 2; u++) {
                const int idx = u * 256 + tid, r = idx >> 4, c = idx & 15;
                uint2 hi, lo; split4(vv[u], hi, lo);
                *(uint2*)&Vh[r * 72 + c * 4] = hi;
                *(uint2*)&Vl[r * 72 + c * 4] = lo;
            }
            __syncthreads();
        }
    }

    const int bb = bh >> 3, hh = bh & 7;
    #pragma unroll
    for (int i = 0; i < 2; i++)
        #pragma unroll
        for (int j = 0; j < 2; j++)
            wmma::store_matrix_sync(
                gctx + ((size_t)bb * T_ + q0 + wm0 + i * 16) * DM_ + hh * DH_ + wn0 + j * 16,
                acc[i][j], DM_, wmma::mem_row_major);
}

// ---------------------------------------------------------------------------

extern "C" void kernel_launch(void* const* d_in, const int* in_sizes, int n_in,
                              void* d_out, int out_size)
{
    const float* Q  = (const float*)d_in[0];
    const float* K  = (const float*)d_in[1];
    const float* V  = (const float*)d_in[2];
    const float* Wq = (const float*)d_in[3];
    const float* bq = (const float*)d_in[4];
    const float* Wk = (const float*)d_in[5];
    const float* bk = (const float*)d_in[6];
    const float* Wv = (const float*)d_in[7];
    const float* bv = (const float*)d_in[8];
    const float* Wo = (const float*)d_in[9];
    const float* bo = (const float*)d_in[10];

    float* out  = (float*)d_out;
    float* attn = out + (size_t)M_ * DM_;   // tuple order: (out, attn)

    float *pq, *pk, *pv, *pctx, *ppart, *pinv;
    cudaGetSymbolAddress((void**)&pq,    g_q);
    cudaGetSymbolAddress((void**)&pk,    g_k);
    cudaGetSymbolAddress((void**)&pv,    g_v);
    cudaGetSymbolAddress((void**)&pctx,  g_ctx);
    cudaGetSymbolAddress((void**)&ppart, g_part);
    cudaGetSymbolAddress((void**)&pinv,  g_inv);

    cudaFuncSetAttribute(qk_kernel, cudaFuncAttributeMaxDynamicSharedMemorySize, QK_SMEM);

    dim3 pgrid(DM_ / 64, M_ / 128);   // (8, 64)

    gemm_proj<<<pgrid, 256>>>(Q, Wq, bq, pq, 0);
    gemm_proj<<<pgrid, 256>>>(K, Wk, bk, pk, 0);
    gemm_proj<<<pgrid, 256>>>(V, Wv, bv, pv, 0);

    qk_kernel<<<dim3(16, 16, 32), 256, QK_SMEM>>>(pq, pk, attn, ppart);
    reduce_kernel<<<BH_ * T_ / 256, 256>>>(ppart, pinv);
    pv_kernel<<<dim3(16, 32), 256>>>(attn, pv, pinv, pctx);

    gemm_proj<<<pgrid, 256>>>(pctx, Wo, bo, out, 2);
}

// round 15
// speedup vs baseline: 1.3104x; 1.3104x over previous
#include <cuda_runtime.h>
#include <cuda_bf16.h>
#include <mma.h>
#include <cstdint>
#include <cstddef>

using namespace nvcuda;

// Problem constants
#define B_   4
#define T_   2048
#define DM_  512
#define H_   8
#define DH_  64
#define BH_  (B_ * H_)     // 32
#define M_   (B_ * T_)     // 8192

// Scratch (device globals; no allocations allowed)
__device__ float g_q  [(size_t)BH_ * T_ * DH_];  // (b,h,t,d)
__device__ float g_k  [(size_t)BH_ * T_ * DH_];  // (b,h,t,d)
__device__ float g_v  [(size_t)BH_ * T_ * DH_];  // (b,h,t,d)
__device__ float g_ctx[(size_t)M_ * DM_];        // (b*T+t, h*64+d)

// fp32 -> bf16 hi + bf16 lo split (hi+lo reproduces fp32 to ~2^-17 rel)
__device__ __forceinline__ void split4(float4 v, uint2& hi, uint2& lo) {
    __nv_bfloat16 h0 = __float2bfloat16(v.x), h1 = __float2bfloat16(v.y);
    __nv_bfloat16 h2 = __float2bfloat16(v.z), h3 = __float2bfloat16(v.w);
    __nv_bfloat16 l0 = __float2bfloat16(v.x - __bfloat162float(h0));
    __nv_bfloat16 l1 = __float2bfloat16(v.y - __bfloat162float(h1));
    __nv_bfloat16 l2 = __float2bfloat16(v.z - __bfloat162float(h2));
    __nv_bfloat16 l3 = __float2bfloat16(v.w - __bfloat162float(h3));
    uint16_t uh0 = *(uint16_t*)&h0, uh1 = *(uint16_t*)&h1;
    uint16_t uh2 = *(uint16_t*)&h2, uh3 = *(uint16_t*)&h3;
    uint16_t ul0 = *(uint16_t*)&l0, ul1 = *(uint16_t*)&l1;
    uint16_t ul2 = *(uint16_t*)&l2, ul3 = *(uint16_t*)&l3;
    hi.x = (uint32_t)uh0 | ((uint32_t)uh1 << 16);
    hi.y = (uint32_t)uh2 | ((uint32_t)uh3 << 16);
    lo.x = (uint32_t)ul0 | ((uint32_t)ul1 << 16);
    lo.y = (uint32_t)ul2 | ((uint32_t)ul3 << 16);
}

typedef wmma::fragment<wmma::matrix_a, 16, 16, 16, __nv_bfloat16, wmma::row_major> FragA;
typedef wmma::fragment<wmma::matrix_b, 16, 16, 16, __nv_bfloat16, wmma::col_major> FragBc;
typedef wmma::fragment<wmma::matrix_b, 16, 16, 16, __nv_bfloat16, wmma::row_major> FragBr;
typedef wmma::fragment<wmma::accumulator, 16, 16, 16, float> FragC;

// ---------------------------------------------------------------------------
// Projection GEMM (wmma split-bf16): out[m,n] = sum_k X[m,k]*W[n,k] + bias[n]
// CTA tile 128(M) x 64(N), BK=32, 256 threads = 8 warps (4m x 2n), warp 32x32.
// mode 0: scatter to (b,h,t,d); mode 2: row-major m*512+n
// ---------------------------------------------------------------------------
__global__ __launch_bounds__(256) void gemm_proj(
    const float* __restrict__ X, const float* __restrict__ W,
    const float* __restrict__ bias, float* __restrict__ out, int mode)
{
    __shared__ __align__(16) char sbuf[36864];
    __nv_bfloat16* Ah = (__nv_bfloat16*)sbuf;      // [128][40]
    __nv_bfloat16* Al = Ah + 5120;
    __nv_bfloat16* Bh = Ah + 10240;                // [64][40]
    __nv_bfloat16* Bl = Ah + 12800;
    float* Cs = (float*)sbuf;                      // [128][72] (epilogue reuse)

    const int tid = threadIdx.x;
    const int wid = tid >> 5;
    const int m0 = blockIdx.y * 128;
    const int n0 = blockIdx.x * 64;
    const int wm0 = (wid >> 1) * 32;
    const int wn0 = (wid & 1) * 32;

    FragC acc[2][2];
    #pragma unroll
    for (int i = 0; i < 2; i++)
        #pragma unroll
        for (int j = 0; j < 2; j++) wmma::fill_fragment(acc[i][j], 0.f);

    float4 px[4], pw[2];

    #pragma unroll
    for (int u = 0; u < 4; u++) {
        const int idx = u * 256 + tid, r = idx >> 3, c = idx & 7;
        px[u] = *(const float4*)&X[(size_t)(m0 + r) * 512 + c * 4];
    }
    #pragma unroll
    for (int u = 0; u < 2; u++) {
        const int idx = u * 256 + tid, r = idx >> 3, c = idx & 7;
        pw[u] = *(const float4*)&W[(size_t)(n0 + r) * 512 + c * 4];
    }
    #pragma unroll
    for (int u = 0; u < 4; u++) {
        const int idx = u * 256 + tid, r = idx >> 3, c = idx & 7;
        uint2 hi, lo; split4(px[u], hi, lo);
        *(uint2*)&Ah[r * 40 + c * 4] = hi;
        *(uint2*)&Al[r * 40 + c * 4] = lo;
    }
    #pragma unroll
    for (int u = 0; u < 2; u++) {
        const int idx = u * 256 + tid, r = idx >> 3, c = idx & 7;
        uint2 hi, lo; split4(pw[u], hi, lo);
        *(uint2*)&Bh[r * 40 + c * 4] = hi;
        *(uint2*)&Bl[r * 40 + c * 4] = lo;
    }
    __syncthreads();

    for (int c0 = 0; c0 < 16; c0++) {
        if (c0 < 15) {
            const int k0 = (c0 + 1) * 32;
            #pragma unroll
            for (int u = 0; u < 4; u++) {
                const int idx = u * 256 + tid, r = idx >> 3, c = idx & 7;
                px[u] = *(const float4*)&X[(size_t)(m0 + r) * 512 + k0 + c * 4];
            }
            #pragma unroll
            for (int u = 0; u < 2; u++) {
                const int idx = u * 256 + tid, r = idx >> 3, c = idx & 7;
                pw[u] = *(const float4*)&W[(size_t)(n0 + r) * 512 + k0 + c * 4];
            }
        }

        #pragma unroll
        for (int ks = 0; ks < 32; ks += 16) {
            FragA ah[2], al[2];
            FragBc bh[2], bl[2];
            #pragma unroll
            for (int i = 0; i < 2; i++) {
                wmma::load_matrix_sync(ah[i], &Ah[(wm0 + i * 16) * 40 + ks], 40);
                wmma::load_matrix_sync(al[i], &Al[(wm0 + i * 16) * 40 + ks], 40);
            }
            #pragma unroll
            for (int j = 0; j < 2; j++) {
                wmma::load_matrix_sync(bh[j], &Bh[(wn0 + j * 16) * 40 + ks], 40);
                wmma::load_matrix_sync(bl[j], &Bl[(wn0 + j * 16) * 40 + ks], 40);
            }
            #pragma unroll
            for (int i = 0; i < 2; i++)
                #pragma unroll
                for (int j = 0; j < 2; j++) {
                    wmma::mma_sync(acc[i][j], ah[i], bh[j], acc[i][j]);
                    wmma::mma_sync(acc[i][j], ah[i], bl[j], acc[i][j]);
                    wmma::mma_sync(acc[i][j], al[i], bh[j], acc[i][j]);
                }
        }
        __syncthreads();
        if (c0 < 15) {
            #pragma unroll
            for (int u = 0; u < 4; u++) {
                const int idx = u * 256 + tid, r = idx >> 3, c = idx & 7;
                uint2 hi, lo; split4(px[u], hi, lo);
                *(uint2*)&Ah[r * 40 + c * 4] = hi;
                *(uint2*)&Al[r * 40 + c * 4] = lo;
            }
            #pragma unroll
            for (int u = 0; u < 2; u++) {
                const int idx = u * 256 + tid, r = idx >> 3, c = idx & 7;
                uint2 hi, lo; split4(pw[u], hi, lo);
                *(uint2*)&Bh[r * 40 + c * 4] = hi;
                *(uint2*)&Bl[r * 40 + c * 4] = lo;
            }
            __syncthreads();
        }
    }

    #pragma unroll
    for (int i = 0; i < 2; i++)
        #pragma unroll
        for (int j = 0; j < 2; j++)
            wmma::store_matrix_sync(&Cs[(wm0 + i * 16) * 72 + wn0 + j * 16],
                                    acc[i][j], 72, wmma::mem_row_major);
    __syncthreads();

    #pragma unroll
    for (int u = 0; u < 8; u++) {
        const int idx = u * 256 + tid;
        const int row = idx >> 4, c4 = idx & 15;
        float4 v = *(const float4*)&Cs[row * 72 + c4 * 4];
        float4 bv = *(const float4*)&bias[n0 + c4 * 4];
        v.x += bv.x; v.y += bv.y; v.z += bv.z; v.w += bv.w;
        const int m = m0 + row;
        size_t o;
        if (mode == 0) {
            const int bb = m >> 11, t = m & 2047, head = n0 >> 6;
            o = (((size_t)bb * H_ + head) * T_ + t) * DH_ + c4 * 4;
        } else {
            o = (size_t)m * DM_ + n0 + c4 * 4;
        }
        *(float4*)&out[o] = v;
    }
}

// ---------------------------------------------------------------------------
// QK kernel: raw scores S[128q][128t] per CTA.
// 512 threads = 16 warps (4m x 4n), warp tile 32x32 (acc 2x2) -> small per-warp
// register state, 16 warps/SM for latency hiding. Direct fp32 fragment stores.
// dynamic smem: Qhi/Qlo/Khi/Klo each [128][72] bf16 = 73728 B
// ---------------------------------------------------------------------------
#define QK_SMEM 73728

__global__ __launch_bounds__(512) void qk_kernel(
    const float* __restrict__ gq, const float* __restrict__ gk,
    float* __restrict__ graw)
{
    extern __shared__ __align__(16) char dsm[];
    __nv_bfloat16* Qh = (__nv_bfloat16*)dsm;   // [128][72]
    __nv_bfloat16* Ql = Qh + 9216;
    __nv_bfloat16* Kh = Qh + 18432;
    __nv_bfloat16* Kl = Qh + 27648;

    const int tid = threadIdx.x;
    const int wid = tid >> 5;
    const int t0 = blockIdx.x * 128;
    const int q0 = blockIdx.y * 128;
    const int bh = blockIdx.z;

    #pragma unroll
    for (int u = 0; u < 4; u++) {
        const int idx = u * 512 + tid, r = idx >> 4, c = idx & 15;
        float4 v = *(const float4*)&gq[((size_t)bh * T_ + q0 + r) * DH_ + c * 4];
        v.x *= 0.125f; v.y *= 0.125f; v.z *= 0.125f; v.w *= 0.125f;
        uint2 hi, lo; split4(v, hi, lo);
        *(uint2*)&Qh[r * 72 + c * 4] = hi;
        *(uint2*)&Ql[r * 72 + c * 4] = lo;
        float4 w = *(const float4*)&gk[((size_t)bh * T_ + t0 + r) * DH_ + c * 4];
        split4(w, hi, lo);
        *(uint2*)&Kh[r * 72 + c * 4] = hi;
        *(uint2*)&Kl[r * 72 + c * 4] = lo;
    }
    __syncthreads();

    const int wm0 = (wid >> 2) * 32;   // 0..96
    const int wn0 = (wid & 3) * 32;    // 0..96

    FragC acc[2][2];
    #pragma unroll
    for (int i = 0; i < 2; i++)
        #pragma unroll
        for (int j = 0; j < 2; j++) wmma::fill_fragment(acc[i][j], 0.f);

    #pragma unroll
    for (int ks = 0; ks < 64; ks += 16) {
        FragA ah[2], al[2];
        #pragma unroll
        for (int i = 0; i < 2; i++) {
            wmma::load_matrix_sync(ah[i], &Qh[(wm0 + i * 16) * 72 + ks], 72);
            wmma::load_matrix_sync(al[i], &Ql[(wm0 + i * 16) * 72 + ks], 72);
        }
        #pragma unroll
        for (int j = 0; j < 2; j++) {
            FragBc bh, bl;
            wmma::load_matrix_sync(bh, &Kh[(wn0 + j * 16) * 72 + ks], 72);
            wmma::load_matrix_sync(bl, &Kl[(wn0 + j * 16) * 72 + ks], 72);
            #pragma unroll
            for (int i = 0; i < 2; i++) {
                wmma::mma_sync(acc[i][j], ah[i], bh, acc[i][j]);
                wmma::mma_sync(acc[i][j], ah[i], bl, acc[i][j]);
                wmma::mma_sync(acc[i][j], al[i], bh, acc[i][j]);
            }
        }
    }

    #pragma unroll
    for (int i = 0; i < 2; i++)
        #pragma unroll
        for (int j = 0; j < 2; j++)
            wmma::store_matrix_sync(
                graw + ((size_t)bh * T_ + q0 + wm0 + i * 16) * T_ + t0 + wn0 + j * 16,
                acc[i][j], T_, wmma::mem_row_major);
}

// ---------------------------------------------------------------------------
// Row softmax in-place: one 256-thread block per row of 2048.
// ---------------------------------------------------------------------------
__global__ __launch_bounds__(256) void softmax_kernel(float* __restrict__ a)
{
    __shared__ float red[8];
    const size_t r = blockIdx.x;
    float4* row = (float4*)(a + r * T_);
    const int tid = threadIdx.x, l = tid & 31, w = tid >> 5;

    float4 v0 = row[tid], v1 = row[tid + 256];
    float mx = fmaxf(fmaxf(fmaxf(v0.x, v0.y), fmaxf(v0.z, v0.w)),
                     fmaxf(fmaxf(v1.x, v1.y), fmaxf(v1.z, v1.w)));
    #pragma unroll
    for (int o = 16; o > 0; o >>= 1) mx = fmaxf(mx, __shfl_xor_sync(0xffffffffu, mx, o));
    if (l == 0) red[w] = mx;
    __syncthreads();
    float m = red[0];
    #pragma unroll
    for (int i = 1; i < 8; i++) m = fmaxf(m, red[i]);
    __syncthreads();

    v0.x = __expf(v0.x - m); v0.y = __expf(v0.y - m);
    v0.z = __expf(v0.z - m); v0.w = __expf(v0.w - m);
    v1.x = __expf(v1.x - m); v1.y = __expf(v1.y - m);
    v1.z = __expf(v1.z - m); v1.w = __expf(v1.w - m);
    float s = v0.x + v0.y + v0.z + v0.w + v1.x + v1.y + v1.z + v1.w;
    #pragma unroll
    for (int o = 16; o > 0; o >>= 1) s += __shfl_xor_sync(0xffffffffu, s, o);
    if (l == 0) red[w] = s;
    __syncthreads();
    float sum = 0.f;
    #pragma unroll
    for (int i = 0; i < 8; i++) sum += red[i];
    const float inv = 1.f / sum;

    v0.x *= inv; v0.y *= inv; v0.z *= inv; v0.w *= inv;
    v1.x *= inv; v1.y *= inv; v1.z *= inv; v1.w *= inv;
    row[tid] = v0; row[tid + 256] = v1;
}

// ---------------------------------------------------------------------------
// PV kernel: ctx[128q][64d] = P[128][2048] @ V[2048][64] per (bh, qb).
// BK=32, 64 chunks, reg prefetch. 8 warps (4m x 2n), warp 32x32 (2x2 frags).
// V consumed row_major (natural (t,d) layout). smem 29696 B static.
// ---------------------------------------------------------------------------
__global__ __launch_bounds__(256) void pv_kernel(
    const float* __restrict__ gp, const float* __restrict__ gv,
    float* __restrict__ gctx)
{
    __shared__ __align__(16) char sbuf[29696];
    __nv_bfloat16* Ph = (__nv_bfloat16*)sbuf;      // [128][40]
    __nv_bfloat16* Pl = Ph + 5120;
    __nv_bfloat16* Vh = Ph + 10240;                // [32][72]
    __nv_bfloat16* Vl = Ph + 12544;

    const int tid = threadIdx.x;
    const int wid = tid >> 5;
    const int q0 = blockIdx.x * 128;
    const int bh = blockIdx.y;
    const int wm0 = (wid >> 1) * 32;
    const int wn0 = (wid & 1) * 32;

    FragC acc[2][2];
    #pragma unroll
    for (int i = 0; i < 2; i++)
        #pragma unroll
        for (int j = 0; j < 2; j++) wmma::fill_fragment(acc[i][j], 0.f);

    float4 pp[4], vv[2];

    // chunk 0 direct
    #pragma unroll
    for (int u = 0; u < 4; u++) {
        const int idx = u * 256 + tid, r = idx >> 3, c = idx & 7;
        pp[u] = *(const float4*)&gp[((size_t)bh * T_ + q0 + r) * T_ + c * 4];
    }
    #pragma unroll
    for (int u = 0; u < 2; u++) {
        const int idx = u * 256 + tid, r = idx >> 4, c = idx & 15;
        vv[u] = *(const float4*)&gv[((size_t)bh * T_ + r) * DH_ + c * 4];
    }
    #pragma unroll
    for (int u = 0; u < 4; u++) {
        const int idx = u * 256 + tid, r = idx >> 3, c = idx & 7;
        uint2 hi, lo; split4(pp[u], hi, lo);
        *(uint2*)&Ph[r * 40 + c * 4] = hi;
        *(uint2*)&Pl[r * 40 + c * 4] = lo;
    }
    #pragma unroll
    for (int u = 0; u < 2; u++) {
        const int idx = u * 256 + tid, r = idx >> 4, c = idx & 15;
        uint2 hi, lo; split4(vv[u], hi, lo);
        *(uint2*)&Vh[r * 72 + c * 4] = hi;
        *(uint2*)&Vl[r * 72 + c * 4] = lo;
    }
    __syncthreads();

    for (int c0 = 0; c0 < 64; c0++) {
        if (c0 < 63) {
            const int tb = (c0 + 1) * 32;
            #pragma unroll
            for (int u = 0; u < 4; u++) {
                const int idx = u * 256 + tid, r = idx >> 3, c = idx & 7;
                pp[u] = *(const float4*)&gp[((size_t)bh * T_ + q0 + r) * T_ + tb + c * 4];
            }
            #pragma unroll
            for (int u = 0; u < 2; u++) {
                const int idx = u * 256 + tid, r = idx >> 4, c = idx & 15;
                vv[u] = *(const float4*)&gv[((size_t)bh * T_ + tb + r) * DH_ + c * 4];
            }
        }

        #pragma unroll
        for (int ks = 0; ks < 32; ks += 16) {
            FragA ah[2], al[2];
            FragBr bh2[2], bl2[2];
            #pragma unroll
            for (int i = 0; i < 2; i++) {
                wmma::load_matrix_sync(ah[i], &Ph[(wm0 + i * 16) * 40 + ks], 40);
                wmma::load_matrix_sync(al[i], &Pl[(wm0 + i * 16) * 40 + ks], 40);
            }
            #pragma unroll
            for (int j = 0; j < 2; j++) {
                wmma::load_matrix_sync(bh2[j], &Vh[ks * 72 + wn0 + j * 16], 72);
                wmma::load_matrix_sync(bl2[j], &Vl[ks * 72 + wn0 + j * 16], 72);
            }
            #pragma unroll
            for (int i = 0; i < 2; i++)
                #pragma unroll
                for (int j = 0; j < 2; j++) {
                    wmma::mma_sync(acc[i][j], ah[i], bh2[j], acc[i][j]);
                    wmma::mma_sync(acc[i][j], ah[i], bl2[j], acc[i][j]);
                    wmma::mma_sync(acc[i][j], al[i], bh2[j], acc[i][j]);
                }
        }
        __syncthreads();
        if (c0 < 63) {
            #pragma unroll
            for (int u = 0; u < 4; u++) {
                const int idx = u * 256 + tid, r = idx >> 3, c = idx & 7;
                uint2 hi, lo; split4(pp[u], hi, lo);
                *(uint2*)&Ph[r * 40 + c * 4] = hi;
                *(uint2*)&Pl[r * 40 + c * 4] = lo;
            }
            #pragma unroll
            for (int u = 0; u < 2; u++) {
                const int idx = u * 256 + tid, r = idx >> 4, c = idx & 15;
                uint2 hi, lo; split4(vv[u], hi, lo);
                *(uint2*)&Vh[r * 72 + c * 4] = hi;
                *(uint2*)&Vl[r * 72 + c * 4] = lo;
            }
            __syncthreads();
        }
    }

    const int bb = bh >> 3, hh = bh & 7;
    #pragma unroll
    for (int i = 0; i < 2; i++)
        #pragma unroll
        for (int j = 0; j < 2; j++)
            wmma::store_matrix_sync(
                gctx + ((size_t)bb * T_ + q0 + wm0 + i * 16) * DM_ + hh * DH_ + wn0 + j * 16,
                acc[i][j], DM_, wmma::mem_row_major);
}

// ---------------------------------------------------------------------------

extern "C" void kernel_launch(void* const* d_in, const int* in_sizes, int n_in,
                              void* d_out, int out_size)
{
    const float* Q  = (const float*)d_in[0];
    const float* K  = (const float*)d_in[1];
    const float* V  = (const float*)d_in[2];
    const float* Wq = (const float*)d_in[3];
    const float* bq = (const float*)d_in[4];
    const float* Wk = (const float*)d_in[5];
    const float* bk = (const float*)d_in[6];
    const float* Wv = (const float*)d_in[7];
    const float* bv = (const float*)d_in[8];
    const float* Wo = (const float*)d_in[9];
    const float* bo = (const float*)d_in[10];

    float* out  = (float*)d_out;
    float* attn = out + (size_t)M_ * DM_;   // tuple order: (out, attn)

    float *pq, *pk, *pv, *pctx;
    cudaGetSymbolAddress((void**)&pq,   g_q);
    cudaGetSymbolAddress((void**)&pk,   g_k);
    cudaGetSymbolAddress((void**)&pv,   g_v);
    cudaGetSymbolAddress((void**)&pctx, g_ctx);

    cudaFuncSetAttribute(qk_kernel, cudaFuncAttributeMaxDynamicSharedMemorySize, QK_SMEM);

    dim3 pgrid(DM_ / 64, M_ / 128);   // (8, 64)

    gemm_proj<<<pgrid, 256>>>(Q, Wq, bq, pq, 0);
    gemm_proj<<<pgrid, 256>>>(K, Wk, bk, pk, 0);
    gemm_proj<<<pgrid, 256>>>(V, Wv, bv, pv, 0);

    qk_kernel<<<dim3(16, 16, 32), 512, QK_SMEM>>>(pq, pk, attn);
    softmax_kernel<<<BH_ * T_, 256>>>(attn);
    pv_kernel<<<dim3(16, 32), 256>>>(attn, pv, pctx);

    gemm_proj<<<pgrid, 256>>>(pctx, Wo, bo, out, 2);
}